// round 1
// baseline (speedup 1.0000x reference)
#include <cuda_runtime.h>

// CosineSim3D: out[b,n,:300] = softmax_n( (a_n . sum_m b_m/|b_m|) / |a_n| )
// B=128, N=M=1024, D=300. Pure HBM-streaming after algebraic collapse.

static constexpr int BATCH   = 128;
static constexpr int NROW    = 1024;
static constexpr int DDIM    = 300;
static constexpr int NQ      = 75;   // float4 per row (300 floats)
static constexpr int NQ_PAD  = 76;   // padded to keep rows 16B-multiple
static constexpr int THREADS = 512;
static constexpr int WARPS   = 16;
static constexpr int RPW     = NROW / WARPS;  // 64 rows per warp
static constexpr int RPI     = 4;             // rows per iteration (MLP batching)

#define EPSV 1e-7f

__device__ __forceinline__ float warp_sum(float v) {
    #pragma unroll
    for (int o = 16; o > 0; o >>= 1) v += __shfl_xor_sync(0xffffffffu, v, o);
    return v;
}
__device__ __forceinline__ float warp_max(float v) {
    #pragma unroll
    for (int o = 16; o > 0; o >>= 1) v = fmaxf(v, __shfl_xor_sync(0xffffffffu, v, o));
    return v;
}
__device__ __forceinline__ float dot4(float4 x, float4 y) {
    return fmaf(x.x, y.x, fmaf(x.y, y.y, fmaf(x.z, y.z, x.w * y.w)));
}
__device__ __forceinline__ void axpy4(float4& acc, float4 q, float s) {
    acc.x = fmaf(q.x, s, acc.x);
    acc.y = fmaf(q.y, s, acc.y);
    acc.z = fmaf(q.z, s, acc.z);
    acc.w = fmaf(q.w, s, acc.w);
}

__global__ void __launch_bounds__(THREADS, 1)
cosine_sim3d_kernel(const float* __restrict__ ga,
                    const float* __restrict__ gb,
                    float* __restrict__ gout)
{
    __shared__ __align__(16) float s_part[WARPS][NQ_PAD * 4];  // 16 x 304 floats
    __shared__ __align__(16) float s_bsum[NQ_PAD * 4];         // 304 floats
    __shared__ float s_scores[NROW];
    __shared__ float s_red[WARPS];

    const int batch = blockIdx.x;
    const int tid   = threadIdx.x;
    const int wid   = tid >> 5;
    const int lane  = tid & 31;
    const bool has_q2 = (lane + 64) < NQ;  // lane < 11

    const float4* a4 = reinterpret_cast<const float4*>(ga) + (size_t)batch * NROW * NQ;
    const float4* b4 = reinterpret_cast<const float4*>(gb) + (size_t)batch * NROW * NQ;
    float4*       o4 = reinterpret_cast<float4*>(gout)     + (size_t)batch * NROW * NQ;

    const int rbase = wid * RPW;
    const float4 f4z = make_float4(0.f, 0.f, 0.f, 0.f);

    // ---------------- Phase 1: bsum = sum_m b[m,:] / ||b[m,:]|| ----------------
    float4 acc0 = f4z, acc1 = f4z, acc2 = f4z;

    #pragma unroll 1
    for (int i = 0; i < RPW; i += RPI) {
        float4 q0[RPI], q1[RPI], q2[RPI];
        #pragma unroll
        for (int r = 0; r < RPI; r++) {
            const float4* row = b4 + (size_t)(rbase + i + r) * NQ;
            q0[r] = row[lane];
            q1[r] = row[lane + 32];
            q2[r] = has_q2 ? row[lane + 64] : f4z;
        }
        #pragma unroll
        for (int r = 0; r < RPI; r++) {
            float ss = dot4(q0[r], q0[r]) + dot4(q1[r], q1[r]) + dot4(q2[r], q2[r]);
            ss = warp_sum(ss);
            float inv = 1.0f / sqrtf(fmaxf(ss, EPSV));
            axpy4(acc0, q0[r], inv);
            axpy4(acc1, q1[r], inv);
            axpy4(acc2, q2[r], inv);
        }
    }

    {
        float4* part4 = reinterpret_cast<float4*>(&s_part[wid][0]);
        part4[lane]      = acc0;
        part4[lane + 32] = acc1;
        if (has_q2) part4[lane + 64] = acc2;
    }
    __syncthreads();

    // deterministic cross-warp reduction (no float atomics)
    if (tid < DDIM) {
        float s = 0.f;
        #pragma unroll
        for (int w = 0; w < WARPS; w++) s += s_part[w][tid];
        s_bsum[tid] = s;
    }
    __syncthreads();

    // ---------------- Phase 2: scores[n] = (a_n . bsum) / ||a_n|| ----------------
    float4 bs0, bs1, bs2;
    {
        const float4* bsum4 = reinterpret_cast<const float4*>(s_bsum);
        bs0 = bsum4[lane];
        bs1 = bsum4[lane + 32];
        bs2 = has_q2 ? bsum4[lane + 64] : f4z;
    }

    #pragma unroll 1
    for (int i = 0; i < RPW; i += RPI) {
        float4 q0[RPI], q1[RPI], q2[RPI];
        #pragma unroll
        for (int r = 0; r < RPI; r++) {
            const float4* row = a4 + (size_t)(rbase + i + r) * NQ;
            q0[r] = row[lane];
            q1[r] = row[lane + 32];
            q2[r] = has_q2 ? row[lane + 64] : f4z;
        }
        #pragma unroll
        for (int r = 0; r < RPI; r++) {
            float ss = dot4(q0[r], q0[r]) + dot4(q1[r], q1[r]) + dot4(q2[r], q2[r]);
            float dt = dot4(q0[r], bs0) + dot4(q1[r], bs1) + dot4(q2[r], bs2);
            #pragma unroll
            for (int o = 16; o > 0; o >>= 1) {
                ss += __shfl_xor_sync(0xffffffffu, ss, o);
                dt += __shfl_xor_sync(0xffffffffu, dt, o);
            }
            if (lane == 0)
                s_scores[rbase + i + r] = dt / sqrtf(fmaxf(ss, EPSV));
        }
    }
    __syncthreads();

    // ---------------- Phase 3: softmax over n (per batch) ----------------
    float v0 = s_scores[tid];
    float v1 = s_scores[tid + THREADS];

    float mx = warp_max(fmaxf(v0, v1));
    if (lane == 0) s_red[wid] = mx;
    __syncthreads();
    if (wid == 0) {
        float m = (lane < WARPS) ? s_red[lane] : -3.4e38f;
        m = warp_max(m);
        if (lane == 0) s_red[0] = m;
    }
    __syncthreads();
    const float gmx = s_red[0];
    __syncthreads();  // everyone has read s_red[0] before it is reused

    float e0 = __expf(v0 - gmx);
    float e1 = __expf(v1 - gmx);
    float sm = warp_sum(e0 + e1);
    if (lane == 0) s_red[wid] = sm;
    __syncthreads();
    if (wid == 0) {
        float s = (lane < WARPS) ? s_red[lane] : 0.f;
        s = warp_sum(s);
        if (lane == 0) s_red[0] = s;
    }
    __syncthreads();
    const float inv_sum = 1.0f / s_red[0];

    s_scores[tid]           = e0 * inv_sum;
    s_scores[tid + THREADS] = e1 * inv_sum;
    __syncthreads();

    // ---------------- Phase 4: tiled broadcast write ----------------
    #pragma unroll 1
    for (int i = 0; i < RPW; i++) {
        const int row = rbase + i;
        const float p = s_scores[row];
        const float4 v = make_float4(p, p, p, p);
        float4* orow = o4 + (size_t)row * NQ;
        orow[lane]      = v;
        orow[lane + 32] = v;
        if (has_q2) orow[lane + 64] = v;
    }
}

extern "C" void kernel_launch(void* const* d_in, const int* in_sizes, int n_in,
                              void* d_out, int out_size) {
    const float* a = (const float*)d_in[0];
    const float* b = (const float*)d_in[1];
    float* out = (float*)d_out;
    cosine_sim3d_kernel<<<BATCH, THREADS>>>(a, b, out);
}